// round 1
// baseline (speedup 1.0000x reference)
#include <cuda_runtime.h>

#define NUM_HEADS 12
#define HEAD_DIM  64
#define SEQ       2048
#define BATCH     2
#define EMB       768
#define SEG       256

// Scratch (allocation-free rule: __device__ globals)
__device__ float g_q[BATCH*NUM_HEADS*SEQ*HEAD_DIM];
__device__ float g_k[BATCH*NUM_HEADS*SEQ*HEAD_DIM];
__device__ float g_v[BATCH*NUM_HEADS*SEQ*HEAD_DIM];
__device__ float g_ctx[BATCH*SEQ*EMB];

// ---------------------------------------------------------------------------
// GEMM core: C[128x128] tile of A[M,K] * W[N,K]^T. BK=8, 256 threads, 8x8 micro.
// As/Bs are [8][132] (pad 4 => conflict-free transposed stores + frag loads).
// ---------------------------------------------------------------------------
__device__ __forceinline__ void gemm_core(const float* __restrict__ A,
                                          const float* __restrict__ W,
                                          int K, int m0, int n0,
                                          float (&acc)[8][8],
                                          float* As, float* Bs) {
  const int tid  = threadIdx.x;
  const int tx   = tid & 15;
  const int ty   = tid >> 4;
  const int lrow = tid >> 1;          // 0..127
  const int lk4  = (tid & 1) << 2;    // 0 or 4
  const float* Aptr = A + (size_t)(m0 + lrow) * K + lk4;
  const float* Wptr = W + (size_t)(n0 + lrow) * K + lk4;

  for (int k0 = 0; k0 < K; k0 += 8) {
    float4 av = *(const float4*)(Aptr + k0);
    float4 bv = *(const float4*)(Wptr + k0);
    As[(lk4+0)*132 + lrow] = av.x;
    As[(lk4+1)*132 + lrow] = av.y;
    As[(lk4+2)*132 + lrow] = av.z;
    As[(lk4+3)*132 + lrow] = av.w;
    Bs[(lk4+0)*132 + lrow] = bv.x;
    Bs[(lk4+1)*132 + lrow] = bv.y;
    Bs[(lk4+2)*132 + lrow] = bv.z;
    Bs[(lk4+3)*132 + lrow] = bv.w;
    __syncthreads();
#pragma unroll
    for (int kk = 0; kk < 8; kk++) {
      float a[8], b[8];
      *(float4*)(a)     = *(const float4*)(As + kk*132 + ty*8);
      *(float4*)(a + 4) = *(const float4*)(As + kk*132 + ty*8 + 4);
      *(float4*)(b)     = *(const float4*)(Bs + kk*132 + tx*8);
      *(float4*)(b + 4) = *(const float4*)(Bs + kk*132 + tx*8 + 4);
#pragma unroll
      for (int i = 0; i < 8; i++)
#pragma unroll
        for (int j = 0; j < 8; j++)
          acc[i][j] += a[i] * b[j];
    }
    __syncthreads();
  }
}

// ---------------------------------------------------------------------------
// QKV projection: y = x @ W^T + b, written in (B,H,S,D) layout.
// grid (6, 32, 3), block 256
// ---------------------------------------------------------------------------
__global__ __launch_bounds__(256) void qkv_kernel(
    const float* __restrict__ x,
    const float* __restrict__ Wq, const float* __restrict__ bq,
    const float* __restrict__ Wk, const float* __restrict__ bk,
    const float* __restrict__ Wv, const float* __restrict__ bv) {
  __shared__ float As[8*132];
  __shared__ float Bs[8*132];
  const int z = blockIdx.z;
  const float* W    = (z == 0) ? Wq : (z == 1) ? Wk : Wv;
  const float* bias = (z == 0) ? bq : (z == 1) ? bk : bv;
  float* outp       = (z == 0) ? g_q : (z == 1) ? g_k : g_v;

  const int m0 = blockIdx.y * 128;
  const int n0 = blockIdx.x * 128;

  float acc[8][8];
#pragma unroll
  for (int i = 0; i < 8; i++)
#pragma unroll
    for (int j = 0; j < 8; j++) acc[i][j] = 0.f;

  gemm_core(x, W, EMB, m0, n0, acc, As, Bs);

  const int tx = threadIdx.x & 15;
  const int ty = threadIdx.x >> 4;
  float bb[8];
  *(float4*)(bb)     = *(const float4*)(bias + n0 + tx*8);
  *(float4*)(bb + 4) = *(const float4*)(bias + n0 + tx*8 + 4);

#pragma unroll
  for (int i = 0; i < 8; i++) {
    const int m  = m0 + ty*8 + i;
    const int bi = m >> 11;       // / SEQ
    const int s  = m & 2047;      // % SEQ
#pragma unroll
    for (int j4 = 0; j4 < 8; j4 += 4) {
      const int n = n0 + tx*8 + j4;
      const int h = n >> 6;
      const int d = n & 63;
      float4 r;
      r.x = acc[i][j4+0] + bb[j4+0];
      r.y = acc[i][j4+1] + bb[j4+1];
      r.z = acc[i][j4+2] + bb[j4+2];
      r.w = acc[i][j4+3] + bb[j4+3];
      *(float4*)(outp + (((size_t)bi*NUM_HEADS + h)*SEQ + s)*HEAD_DIM + d) = r;
    }
  }
}

// ---------------------------------------------------------------------------
// Output projection: out = ctx @ Wo^T + bo, row-major (B*S, E). grid (6,32)
// ---------------------------------------------------------------------------
__global__ __launch_bounds__(256) void out_kernel(
    const float* __restrict__ Wo, const float* __restrict__ bo,
    float* __restrict__ out) {
  __shared__ float As[8*132];
  __shared__ float Bs[8*132];
  const int m0 = blockIdx.y * 128;
  const int n0 = blockIdx.x * 128;

  float acc[8][8];
#pragma unroll
  for (int i = 0; i < 8; i++)
#pragma unroll
    for (int j = 0; j < 8; j++) acc[i][j] = 0.f;

  gemm_core(g_ctx, Wo, EMB, m0, n0, acc, As, Bs);

  const int tx = threadIdx.x & 15;
  const int ty = threadIdx.x >> 4;
  float bb[8];
  *(float4*)(bb)     = *(const float4*)(bo + n0 + tx*8);
  *(float4*)(bb + 4) = *(const float4*)(bo + n0 + tx*8 + 4);

#pragma unroll
  for (int i = 0; i < 8; i++) {
    const int m = m0 + ty*8 + i;
#pragma unroll
    for (int j4 = 0; j4 < 8; j4 += 4) {
      const int n = n0 + tx*8 + j4;
      float4 r;
      r.x = acc[i][j4+0] + bb[j4+0];
      r.y = acc[i][j4+1] + bb[j4+1];
      r.z = acc[i][j4+2] + bb[j4+2];
      r.w = acc[i][j4+3] + bb[j4+3];
      *(float4*)(out + (size_t)m*EMB + n) = r;
    }
  }
}

// ---------------------------------------------------------------------------
// Segment-local attention. DILATION=1 => mask is block-diagonal over 256-token
// segments; all entries in-segment are valid.
// One CTA per (b, h, seg, qtile of 64 rows): grid 768, block 256.
// smem: Qt[64][68] (d-major), Kt[64][256] (d-major), Vs[256][68], Pt[256][68]
// ---------------------------------------------------------------------------
#define SMEM_FLOATS (64*68 + 64*256 + 256*68 + 256*68 + 64)
#define SMEM_BYTES  (SMEM_FLOATS * 4)

__global__ __launch_bounds__(256) void attn_kernel() {
  extern __shared__ float sm[];
  float* Qt   = sm;                    // 64*68
  float* Kt   = Qt + 64*68;            // 64*256
  float* Vs   = Kt + 64*256;           // 256*68
  float* Pt   = Vs + 256*68;           // 256*68
  float* rinv = Pt + 256*68;           // 64

  const int tid = threadIdx.x;
  int bx = blockIdx.x;
  const int qt  = bx & 3;   bx >>= 2;
  const int seg = bx & 7;   bx >>= 3;
  const int hh  = bx % NUM_HEADS;
  const int bb  = bx / NUM_HEADS;

  const size_t head_off = (((size_t)bb*NUM_HEADS + hh)*SEQ + seg*SEG) * HEAD_DIM;
  const float* qbase = g_q + head_off + (size_t)qt*64*HEAD_DIM;
  const float* kbase = g_k + head_off;
  const float* vbase = g_v + head_off;

  // Load K (transposed, d-major) and V (row-major) — one row per thread.
  {
    const int j = tid;
#pragma unroll
    for (int u = 0; u < 16; u++) {
      float4 kv = *(const float4*)(kbase + j*64 + u*4);
      Kt[(u*4+0)*256 + j] = kv.x;
      Kt[(u*4+1)*256 + j] = kv.y;
      Kt[(u*4+2)*256 + j] = kv.z;
      Kt[(u*4+3)*256 + j] = kv.w;
      float4 vv = *(const float4*)(vbase + j*64 + u*4);
      *(float4*)(Vs + j*68 + u*4) = vv;
    }
  }
  // Load Q (transposed, pre-scaled by 1/sqrt(64) = 0.125)
  {
    const int r  = tid & 63;
    const int qu = tid >> 6;
#pragma unroll
    for (int u = 0; u < 4; u++) {
      const int d0 = qu*16 + u*4;
      float4 qv = *(const float4*)(qbase + r*64 + d0);
      Qt[(d0+0)*68 + r] = qv.x * 0.125f;
      Qt[(d0+1)*68 + r] = qv.y * 0.125f;
      Qt[(d0+2)*68 + r] = qv.z * 0.125f;
      Qt[(d0+3)*68 + r] = qv.w * 0.125f;
    }
  }
  __syncthreads();

  // Scores: Pt[j][r] = (Q/8) . K  ; thread handles j in {tj+32u}, r in tr*8..+7
  {
    const int tj = tid & 31;
    const int tr = tid >> 5;
    float acc[8][8];
#pragma unroll
    for (int u = 0; u < 8; u++)
#pragma unroll
      for (int ri = 0; ri < 8; ri++) acc[u][ri] = 0.f;

    for (int d = 0; d < 64; d++) {
      float qf[8];
      *(float4*)(qf)     = *(const float4*)(Qt + d*68 + tr*8);
      *(float4*)(qf + 4) = *(const float4*)(Qt + d*68 + tr*8 + 4);
#pragma unroll
      for (int u = 0; u < 8; u++) {
        const float kf = Kt[d*256 + tj + 32*u];
#pragma unroll
        for (int ri = 0; ri < 8; ri++) acc[u][ri] += kf * qf[ri];
      }
    }
#pragma unroll
    for (int u = 0; u < 8; u++) {
      const int j = tj + 32*u;
      *(float4*)(Pt + j*68 + tr*8)     = make_float4(acc[u][0], acc[u][1], acc[u][2], acc[u][3]);
      *(float4*)(Pt + j*68 + tr*8 + 4) = make_float4(acc[u][4], acc[u][5], acc[u][6], acc[u][7]);
    }
  }
  __syncthreads();

  // Softmax (2-pass; inv-sum deferred to PV epilogue). 4 lanes per row.
  {
    const int r = tid >> 2;
    const int c = tid & 3;
    float mx = -1e30f;
    for (int jj = 0; jj < 64; jj++)
      mx = fmaxf(mx, Pt[(c*64 + jj)*68 + r]);
    mx = fmaxf(mx, __shfl_xor_sync(0xffffffffu, mx, 1));
    mx = fmaxf(mx, __shfl_xor_sync(0xffffffffu, mx, 2));
    float ssum = 0.f;
    for (int jj = 0; jj < 64; jj++) {
      const int idx = (c*64 + jj)*68 + r;
      const float e = __expf(Pt[idx] - mx);
      Pt[idx] = e;
      ssum += e;
    }
    ssum += __shfl_xor_sync(0xffffffffu, ssum, 1);
    ssum += __shfl_xor_sync(0xffffffffu, ssum, 2);
    if (c == 0) rinv[r] = 1.0f / ssum;
  }
  __syncthreads();

  // PV: ctx[r][d] = (1/sum_r) * sum_j P[r][j] * V[j][d]
  {
    const int tc  = tid & 15;   // d block of 4
    const int tr2 = tid >> 4;   // r block of 4
    float acc[4][4];
#pragma unroll
    for (int i = 0; i < 4; i++)
#pragma unroll
      for (int j = 0; j < 4; j++) acc[i][j] = 0.f;

    for (int j = 0; j < 256; j++) {
      float pf[4], vf[4];
      *(float4*)pf = *(const float4*)(Pt + j*68 + tr2*4);
      *(float4*)vf = *(const float4*)(Vs + j*68 + tc*4);
#pragma unroll
      for (int i = 0; i < 4; i++)
#pragma unroll
        for (int jj = 0; jj < 4; jj++) acc[i][jj] += pf[i] * vf[jj];
    }

    float* ctxbase = g_ctx + ((size_t)bb*SEQ + seg*SEG + qt*64)*EMB + hh*64;
#pragma unroll
    for (int i = 0; i < 4; i++) {
      const int row  = tr2*4 + i;
      const float iv = rinv[row];
      float4 o = make_float4(acc[i][0]*iv, acc[i][1]*iv, acc[i][2]*iv, acc[i][3]*iv);
      *(float4*)(ctxbase + (size_t)row*EMB + tc*4) = o;
    }
  }
}

// ---------------------------------------------------------------------------
extern "C" void kernel_launch(void* const* d_in, const int* in_sizes, int n_in,
                              void* d_out, int out_size) {
  const float* x  = (const float*)d_in[0];
  const float* Wq = (const float*)d_in[1];
  const float* bq = (const float*)d_in[2];
  const float* Wk = (const float*)d_in[3];
  const float* bk = (const float*)d_in[4];
  const float* Wv = (const float*)d_in[5];
  const float* bv = (const float*)d_in[6];
  const float* Wo = (const float*)d_in[7];
  const float* bo = (const float*)d_in[8];
  float* out = (float*)d_out;

  cudaFuncSetAttribute(attn_kernel,
                       cudaFuncAttributeMaxDynamicSharedMemorySize, SMEM_BYTES);

  dim3 gqkv(6, 32, 3);
  qkv_kernel<<<gqkv, 256>>>(x, Wq, bq, Wk, bk, Wv, bv);

  attn_kernel<<<768, 256, SMEM_BYTES>>>();

  dim3 gout(6, 32, 1);
  out_kernel<<<gout, 256>>>(Wo, bo, out);
}

// round 4
// speedup vs baseline: 1.2793x; 1.2793x over previous
#include <cuda_runtime.h>
#include <cuda_bf16.h>
#include <cstdint>

#define NUM_HEADS 12
#define HEAD_DIM  64
#define SEQ       2048
#define BATCH     2
#define EMB       768
#define SEG       256
#define KDIM      768

// Scratch (allocation-free rule: __device__ globals)
__device__ float g_q[BATCH*NUM_HEADS*SEQ*HEAD_DIM];
__device__ float g_k[BATCH*NUM_HEADS*SEQ*HEAD_DIM];
__device__ float g_v[BATCH*NUM_HEADS*SEQ*HEAD_DIM];
__device__ float g_ctx[BATCH*SEQ*EMB];

// ===========================================================================
// Warp-level MMA helpers (compute_100-safe: sm_80-era PTX)
// ===========================================================================
__device__ __forceinline__ uint32_t smem_u32(const void* p) {
  uint32_t a;
  asm("{ .reg .u64 t; cvta.to.shared.u64 t, %1; cvt.u32.u64 %0, t; }" : "=r"(a) : "l"(p));
  return a;
}

__device__ __forceinline__ void ldsm4(uint32_t* r, uint32_t addr) {
  asm volatile("ldmatrix.sync.aligned.m8n8.x4.shared.b16 {%0,%1,%2,%3}, [%4];"
               : "=r"(r[0]), "=r"(r[1]), "=r"(r[2]), "=r"(r[3]) : "r"(addr));
}

__device__ __forceinline__ void mma_bf16(float* d, const uint32_t* a,
                                         uint32_t b0, uint32_t b1) {
  asm volatile(
      "mma.sync.aligned.m16n8k16.row.col.f32.bf16.bf16.f32 "
      "{%0,%1,%2,%3}, {%4,%5,%6,%7}, {%8,%9}, {%0,%1,%2,%3};"
      : "+f"(d[0]), "+f"(d[1]), "+f"(d[2]), "+f"(d[3])
      : "r"(a[0]), "r"(a[1]), "r"(a[2]), "r"(a[3]), "r"(b0), "r"(b1));
}

#define SWZ(off) ((off) ^ (((off) >> 3) & 0x70))

// ===========================================================================
// GEMM: C[m][n] = sum_k A[m][k] * W[n][k] + bias[n]
// Split-precision bf16 (hi*hi + hi*lo + lo*hi), fp32 register accumulators.
// CTA tile 128x128, K chunked by 64. 256 threads, warp grid 4(M) x 2(N),
// warp tile 32x64 (2 m-atoms x 8 n-atoms of m16n8k16).
// mode 0: QKV (blockIdx.z selects q/k/v, scatter to (B,H,S,D))
// mode 1: out projection (row-major to dout)
// ===========================================================================
#define GK      64
#define NCHUNK  (KDIM / GK)            // 12
#define TILE_B  16384                  // 128 rows * 64 bf16 * 2B
#define OFF_AHI 0
#define OFF_ALO (OFF_AHI + TILE_B)
#define OFF_BHI (OFF_ALO + TILE_B)
#define OFF_BLO (OFF_BHI + TILE_B)
#define GEMM_SMEM (OFF_BLO + TILE_B)   // 65536

__device__ __forceinline__ uint32_t pack2(float a, float b) {
  __nv_bfloat162 p = __halves2bfloat162(__float2bfloat16(a), __float2bfloat16(b));
  return *reinterpret_cast<uint32_t*>(&p);
}

__global__ __launch_bounds__(256) void gemm_hmma_kernel(
    const float* __restrict__ A0,
    const float* __restrict__ W0, const float* __restrict__ b0,
    const float* __restrict__ W1, const float* __restrict__ b1,
    const float* __restrict__ W2, const float* __restrict__ b2,
    float* __restrict__ dout, int mode) {
  extern __shared__ char sm[];
  const uint32_t sbase = smem_u32(sm);
  const int tid  = threadIdx.x;
  const int wid  = tid >> 5;
  const int lane = tid & 31;
  const int m0 = blockIdx.y * 128;
  const int n0 = blockIdx.x * 128;
  const int z  = blockIdx.z;

  const float* A    = (mode == 1) ? g_ctx : A0;
  const float* W    = (z == 0) ? W0 : (z == 1) ? W1 : W2;
  const float* bias = (z == 0) ? b0 : (z == 1) ? b1 : b2;
  float* outp = (mode == 1) ? dout : ((z == 0) ? g_q : (z == 1) ? g_k : g_v);

  // staging indices: thread covers tile row r, K half cb
  const int r  = tid >> 1;           // 0..127
  const int cb = (tid & 1) * 32;     // 0 or 32
  const float* Ap = A + (size_t)(m0 + r) * KDIM + cb;
  const float* Wp = W + (size_t)(n0 + r) * KDIM + cb;

  // warp tile position
  const int mw = (wid >> 1) * 32;    // 0,32,64,96
  const int nw = (wid & 1) * 64;     // 0,64

  // ldmatrix lane addressing: row-in-16 and k-block byte offset
  const int lrow = lane & 15;
  const int lkb  = (lane >> 4) * 16; // 8 bf16 = 16B

  float acc[16][4];                  // [mi*8+ni][4]
#pragma unroll
  for (int i = 0; i < 16; i++)
#pragma unroll
    for (int j = 0; j < 4; j++) acc[i][j] = 0.f;

  for (int c = 0; c < NCHUNK; c++) {
    // ---- stage: fp32 -> bf16 hi/lo, swizzled K-major (64 bf16/row) ----
#pragma unroll
    for (int u = 0; u < 8; u++) {
      float4 av = *(const float4*)(Ap + c * GK + u * 4);
      float4 wv = *(const float4*)(Wp + c * GK + u * 4);
      const uint32_t boff = (uint32_t)(r * 128 + (cb + u * 4) * 2);
      const uint32_t sw = SWZ(boff);

      float ahx = __bfloat162float(__float2bfloat16(av.x));
      float ahy = __bfloat162float(__float2bfloat16(av.y));
      float ahz = __bfloat162float(__float2bfloat16(av.z));
      float ahw = __bfloat162float(__float2bfloat16(av.w));
      *(uint2*)(sm + OFF_AHI + sw) = make_uint2(pack2(ahx, ahy), pack2(ahz, ahw));
      *(uint2*)(sm + OFF_ALO + sw) =
          make_uint2(pack2(av.x - ahx, av.y - ahy), pack2(av.z - ahz, av.w - ahw));

      float whx = __bfloat162float(__float2bfloat16(wv.x));
      float why = __bfloat162float(__float2bfloat16(wv.y));
      float whz = __bfloat162float(__float2bfloat16(wv.z));
      float whw = __bfloat162float(__float2bfloat16(wv.w));
      *(uint2*)(sm + OFF_BHI + sw) = make_uint2(pack2(whx, why), pack2(whz, whw));
      *(uint2*)(sm + OFF_BLO + sw) =
          make_uint2(pack2(wv.x - whx, wv.y - why), pack2(wv.z - whz, wv.w - whw));
    }
    __syncthreads();

    // ---- compute: 4 K16 steps, 48 mma each ----
#pragma unroll
    for (int ks = 0; ks < 4; ks++) {
      const uint32_t koff = (uint32_t)(ks * 32 + lkb);
      uint32_t ah[2][4], al[2][4];
#pragma unroll
      for (int mi = 0; mi < 2; mi++) {
        const uint32_t off = (uint32_t)((mw + mi * 16 + lrow) * 128) + koff;
        ldsm4(ah[mi], sbase + OFF_AHI + SWZ(off));
        ldsm4(al[mi], sbase + OFF_ALO + SWZ(off));
      }
      uint32_t bh[4][4], bl[4][4];
#pragma unroll
      for (int nb = 0; nb < 4; nb++) {
        const uint32_t off = (uint32_t)((nw + nb * 16 + lrow) * 128) + koff;
        ldsm4(bh[nb], sbase + OFF_BHI + SWZ(off));
        ldsm4(bl[nb], sbase + OFF_BLO + SWZ(off));
      }
#pragma unroll
      for (int ni = 0; ni < 8; ni++) {
        const int nb = ni >> 1, sel = ni & 1;
        const uint32_t bh0 = bh[nb][sel], bh1 = bh[nb][2 + sel];
        const uint32_t bl0 = bl[nb][sel], bl1 = bl[nb][2 + sel];
#pragma unroll
        for (int mi = 0; mi < 2; mi++) {
          mma_bf16(acc[mi * 8 + ni], ah[mi], bh0, bh1);  // hi*hi
          mma_bf16(acc[mi * 8 + ni], ah[mi], bl0, bl1);  // hi*lo
          mma_bf16(acc[mi * 8 + ni], al[mi], bh0, bh1);  // lo*hi
        }
      }
    }
    __syncthreads();
  }

  // ---- epilogue: bias add + store ----
  const int er = lane >> 2;        // 0..7
  const int ec = (lane & 3) * 2;   // 0,2,4,6
#pragma unroll
  for (int mi = 0; mi < 2; mi++) {
#pragma unroll
    for (int rr = 0; rr < 2; rr++) {
      const int m = m0 + mw + mi * 16 + rr * 8 + er;
      if (mode == 1) {
        float* orow = outp + (size_t)m * EMB;
#pragma unroll
        for (int ni = 0; ni < 8; ni++) {
          const int n = n0 + nw + ni * 8 + ec;
          float2 v;
          v.x = acc[mi * 8 + ni][rr * 2 + 0] + bias[n];
          v.y = acc[mi * 8 + ni][rr * 2 + 1] + bias[n + 1];
          *(float2*)(orow + n) = v;
        }
      } else {
        const int b = m >> 11;
        const int s = m & 2047;
#pragma unroll
        for (int ni = 0; ni < 8; ni++) {
          const int n = n0 + nw + ni * 8 + ec;
          const int h = n >> 6;
          const int d = n & 63;
          float2 v;
          v.x = acc[mi * 8 + ni][rr * 2 + 0] + bias[n];
          v.y = acc[mi * 8 + ni][rr * 2 + 1] + bias[n + 1];
          *(float2*)(outp + (((size_t)b * NUM_HEADS + h) * SEQ + s) * HEAD_DIM + d) = v;
        }
      }
    }
  }
}

// ===========================================================================
// Segment-local attention (R1-proven). DILATION=1 => block-diagonal.
// One CTA per (b, h, seg, qtile of 64 rows): grid 768, block 256.
// ===========================================================================
#define SMEM_FLOATS (64*68 + 64*256 + 256*68 + 256*68 + 64)
#define SMEM_BYTES  (SMEM_FLOATS * 4)

__global__ __launch_bounds__(256) void attn_kernel() {
  extern __shared__ float smf[];
  float* Qt   = smf;
  float* Kt   = Qt + 64*68;
  float* Vs   = Kt + 64*256;
  float* Pt   = Vs + 256*68;
  float* rinv = Pt + 256*68;

  const int tid = threadIdx.x;
  int bx = blockIdx.x;
  const int qt  = bx & 3;   bx >>= 2;
  const int seg = bx & 7;   bx >>= 3;
  const int hh  = bx % NUM_HEADS;
  const int bb  = bx / NUM_HEADS;

  const size_t head_off = (((size_t)bb*NUM_HEADS + hh)*SEQ + seg*SEG) * HEAD_DIM;
  const float* qbase = g_q + head_off + (size_t)qt*64*HEAD_DIM;
  const float* kbase = g_k + head_off;
  const float* vbase = g_v + head_off;

  {
    const int j = tid;
#pragma unroll
    for (int u = 0; u < 16; u++) {
      float4 kv = *(const float4*)(kbase + j*64 + u*4);
      Kt[(u*4+0)*256 + j] = kv.x;
      Kt[(u*4+1)*256 + j] = kv.y;
      Kt[(u*4+2)*256 + j] = kv.z;
      Kt[(u*4+3)*256 + j] = kv.w;
      float4 vv = *(const float4*)(vbase + j*64 + u*4);
      *(float4*)(Vs + j*68 + u*4) = vv;
    }
  }
  {
    const int r  = tid & 63;
    const int qu = tid >> 6;
#pragma unroll
    for (int u = 0; u < 4; u++) {
      const int d0 = qu*16 + u*4;
      float4 qv = *(const float4*)(qbase + r*64 + d0);
      Qt[(d0+0)*68 + r] = qv.x * 0.125f;
      Qt[(d0+1)*68 + r] = qv.y * 0.125f;
      Qt[(d0+2)*68 + r] = qv.z * 0.125f;
      Qt[(d0+3)*68 + r] = qv.w * 0.125f;
    }
  }
  __syncthreads();

  {
    const int tj = tid & 31;
    const int tr = tid >> 5;
    float acc[8][8];
#pragma unroll
    for (int u = 0; u < 8; u++)
#pragma unroll
      for (int ri = 0; ri < 8; ri++) acc[u][ri] = 0.f;

    for (int d = 0; d < 64; d++) {
      float qf[8];
      *(float4*)(qf)     = *(const float4*)(Qt + d*68 + tr*8);
      *(float4*)(qf + 4) = *(const float4*)(Qt + d*68 + tr*8 + 4);
#pragma unroll
      for (int u = 0; u < 8; u++) {
        const float kf = Kt[d*256 + tj + 32*u];
#pragma unroll
        for (int ri = 0; ri < 8; ri++) acc[u][ri] += kf * qf[ri];
      }
    }
#pragma unroll
    for (int u = 0; u < 8; u++) {
      const int j = tj + 32*u;
      *(float4*)(Pt + j*68 + tr*8)     = make_float4(acc[u][0], acc[u][1], acc[u][2], acc[u][3]);
      *(float4*)(Pt + j*68 + tr*8 + 4) = make_float4(acc[u][4], acc[u][5], acc[u][6], acc[u][7]);
    }
  }
  __syncthreads();

  {
    const int r = tid >> 2;
    const int c = tid & 3;
    float mx = -1e30f;
    for (int jj = 0; jj < 64; jj++)
      mx = fmaxf(mx, Pt[(c*64 + jj)*68 + r]);
    mx = fmaxf(mx, __shfl_xor_sync(0xffffffffu, mx, 1));
    mx = fmaxf(mx, __shfl_xor_sync(0xffffffffu, mx, 2));
    float ssum = 0.f;
    for (int jj = 0; jj < 64; jj++) {
      const int idx = (c*64 + jj)*68 + r;
      const float e = __expf(Pt[idx] - mx);
      Pt[idx] = e;
      ssum += e;
    }
    ssum += __shfl_xor_sync(0xffffffffu, ssum, 1);
    ssum += __shfl_xor_sync(0xffffffffu, ssum, 2);
    if (c == 0) rinv[r] = 1.0f / ssum;
  }
  __syncthreads();

  {
    const int tc  = tid & 15;
    const int tr2 = tid >> 4;
    float acc[4][4];
#pragma unroll
    for (int i = 0; i < 4; i++)
#pragma unroll
      for (int j = 0; j < 4; j++) acc[i][j] = 0.f;

    for (int j = 0; j < 256; j++) {
      float pf[4], vf[4];
      *(float4*)pf = *(const float4*)(Pt + j*68 + tr2*4);
      *(float4*)vf = *(const float4*)(Vs + j*68 + tc*4);
#pragma unroll
      for (int i = 0; i < 4; i++)
#pragma unroll
        for (int jj = 0; jj < 4; jj++) acc[i][jj] += pf[i] * vf[jj];
    }

    float* ctxbase = g_ctx + ((size_t)bb*SEQ + seg*SEG + qt*64)*EMB + hh*64;
#pragma unroll
    for (int i = 0; i < 4; i++) {
      const int row  = tr2*4 + i;
      const float iv = rinv[row];
      float4 o = make_float4(acc[i][0]*iv, acc[i][1]*iv, acc[i][2]*iv, acc[i][3]*iv);
      *(float4*)(ctxbase + (size_t)row*EMB + tc*4) = o;
    }
  }
}

// ===========================================================================
extern "C" void kernel_launch(void* const* d_in, const int* in_sizes, int n_in,
                              void* d_out, int out_size) {
  const float* x  = (const float*)d_in[0];
  const float* Wq = (const float*)d_in[1];
  const float* bq = (const float*)d_in[2];
  const float* Wk = (const float*)d_in[3];
  const float* bk = (const float*)d_in[4];
  const float* Wv = (const float*)d_in[5];
  const float* bv = (const float*)d_in[6];
  const float* Wo = (const float*)d_in[7];
  const float* bo = (const float*)d_in[8];
  float* out = (float*)d_out;

  cudaFuncSetAttribute(gemm_hmma_kernel,
                       cudaFuncAttributeMaxDynamicSharedMemorySize, GEMM_SMEM);
  cudaFuncSetAttribute(attn_kernel,
                       cudaFuncAttributeMaxDynamicSharedMemorySize, SMEM_BYTES);

  dim3 gqkv(6, 32, 3);
  gemm_hmma_kernel<<<gqkv, 256, GEMM_SMEM>>>(x, Wq, bq, Wk, bk, Wv, bv,
                                             nullptr, 0);

  attn_kernel<<<768, 256, SMEM_BYTES>>>();

  dim3 gout(6, 32, 1);
  gemm_hmma_kernel<<<gout, 256, GEMM_SMEM>>>(nullptr, Wo, bo, Wo, bo, Wo, bo,
                                             out, 1);
}